// round 1
// baseline (speedup 1.0000x reference)
#include <cuda_runtime.h>
#include <math.h>

#define BB 64
#define SS 96
#define HH 1024
#define EE 512
#define VV 32000
#define TT 32
#define G3 3072
#define NLBLK 250   // 32000 / 128

// ---------------- device scratch (static, no allocations) ----------------
__device__ float g_u[HH];                 // u = Ua^T @ Va
__device__ float g_ctx[BB * HH];          // attention context (step-invariant)
__device__ float g_gictx[BB * G3];        // ctx @ W_ih[:,E:]^T (step-invariant)
__device__ float g_giacc[BB * G3];        // per-step emb @ W_ih[:, :E]^T
__device__ float g_ghacc[BB * G3];        // per-step h @ W_hh^T
__device__ float g_h[2][BB * HH];         // hidden state ping-pong
__device__ int   g_tok[BB];               // current tokens
__device__ float g_pv[BB * NLBLK];        // argmax partials (value)
__device__ int   g_pi[BB * NLBLK];        // argmax partials (index)

// ---------------- packed fp32x2 FMA (Blackwell) ----------------
union F2U { float2 f; unsigned long long u; };
__device__ __forceinline__ float2 ffma2(float2 a, float2 b, float2 c) {
    F2U A, B, C, D;
    A.f = a; B.f = b; C.f = c;
    asm("fma.rn.f32x2 %0, %1, %2, %3;" : "=l"(D.u) : "l"(A.u), "l"(B.u), "l"(C.u));
    return D.f;
}

// ---------------- init: h0 <- encoder_hidden, tok <- START ----------------
__global__ void k_init(const float* __restrict__ eh) {
    int i = blockIdx.x * blockDim.x + threadIdx.x;
    if (i < BB * HH) g_h[0][i] = eh[i];
    if (i < BB)      g_tok[i] = 1;
}

// ---------------- u[h] = sum_g Va[g] * Ua[g,h] ----------------
__global__ void __launch_bounds__(256) k_u(const float* __restrict__ Ua,
                                           const float* __restrict__ Va) {
    __shared__ float sva[HH];
    for (int i = threadIdx.x; i < HH; i += 256) sva[i] = Va[i];
    __syncthreads();
    int h = blockIdx.x * 256 + threadIdx.x;
    float acc = 0.f;
    for (int g = 0; g < HH; ++g) acc = fmaf(sva[g], Ua[(size_t)g * HH + h], acc);
    g_u[h] = acc;
}

// ---------------- attention: scores, softmax, ctx, write attentions ----------------
__global__ void __launch_bounds__(128) k_attn(const float* __restrict__ keys,
                                              float* __restrict__ out_attn) {
    __shared__ float s_w[SS];
    __shared__ float s_u[HH];
    int b = blockIdx.x, tid = threadIdx.x;
    for (int i = tid; i < HH; i += 128) s_u[i] = g_u[i];
    __syncthreads();

    int warp = tid >> 5, lane = tid & 31;
    const float* kb = keys + (size_t)b * SS * HH;

    for (int s = warp; s < SS; s += 4) {
        const float* kr = kb + (size_t)s * HH;
        float acc = 0.f;
        for (int k = lane; k < HH; k += 32) acc = fmaf(kr[k], s_u[k], acc);
        #pragma unroll
        for (int o = 16; o; o >>= 1) acc += __shfl_down_sync(0xffffffffu, acc, o);
        if (!lane) s_w[s] = acc;
    }
    __syncthreads();

    if (warp == 0) {
        float m = -1e30f;
        for (int s = lane; s < SS; s += 32) m = fmaxf(m, s_w[s]);
        #pragma unroll
        for (int o = 16; o; o >>= 1) m = fmaxf(m, __shfl_xor_sync(0xffffffffu, m, o));
        float sum = 0.f;
        for (int s = lane; s < SS; s += 32) { float e = expf(s_w[s] - m); s_w[s] = e; sum += e; }
        #pragma unroll
        for (int o = 16; o; o >>= 1) sum += __shfl_xor_sync(0xffffffffu, sum, o);
        float inv = 1.f / sum;
        for (int s = lane; s < SS; s += 32) s_w[s] *= inv;
    }
    __syncthreads();

    // ctx[b,h] = sum_s w[s]*keys[b,s,h]
    for (int h = tid; h < HH; h += 128) {
        float acc = 0.f;
        for (int s = 0; s < SS; ++s) acc = fmaf(s_w[s], kb[(size_t)s * HH + h], acc);
        g_ctx[b * HH + h] = acc;
    }
    // attentions are step-invariant: replicate over T
    float* oa = out_attn + (size_t)b * TT * SS;
    for (int e = tid; e < TT * SS; e += 128) oa[e] = s_w[e % SS];
}

// ---------------- generic 64(b) x 32(rows) GEMM tile, K-loop, f32x2 ----------------
// C[b*G3 + j0+r] += sum_k A(b,k) * W[(j0+r)*ldw + woff + k]
// A mode: Aptr != null -> dense [64,K]; else emb-gather: relu(emb_table[tok[b]*EE + k])
#define KT 32
__device__ __forceinline__ void gemm64x32(
    const float* __restrict__ Aptr, const float* __restrict__ emb_table,
    const float* __restrict__ W, int ldw, int woff,
    int j0, int K, float* __restrict__ C)
{
    __shared__ float As[KT][68];
    __shared__ float Ws[KT][36];
    __shared__ int stok[BB];
    const int tid = threadIdx.x;  // 128 threads
    if (Aptr == nullptr && tid < BB) stok[tid] = g_tok[tid];
    __syncthreads();

    const int rthr = tid & 15, bthr = tid >> 4;
    const int r0 = rthr * 2, b0 = bthr * 8;
    float2 acc[2][4] = {};

    for (int k0 = 0; k0 < K; k0 += KT) {
        // A tile: 64 x 32 = 2048 floats, 4 float4 per thread
        #pragma unroll
        for (int r = 0; r < 4; ++r) {
            int idx = r * 128 + tid;
            int bb = idx & 63, k4 = (idx >> 6) * 4;
            float4 v;
            if (Aptr) v = *(const float4*)(Aptr + (size_t)bb * K + k0 + k4);
            else {
                v = *(const float4*)(emb_table + (size_t)stok[bb] * EE + k0 + k4);
                v.x = fmaxf(v.x, 0.f); v.y = fmaxf(v.y, 0.f);
                v.z = fmaxf(v.z, 0.f); v.w = fmaxf(v.w, 0.f);
            }
            As[k4 + 0][bb] = v.x; As[k4 + 1][bb] = v.y;
            As[k4 + 2][bb] = v.z; As[k4 + 3][bb] = v.w;
        }
        // W tile: 32 rows x 32 k = 1024 floats, 2 float4 per thread
        #pragma unroll
        for (int r = 0; r < 2; ++r) {
            int idx = r * 128 + tid;
            int rr = idx & 31, k4 = (idx >> 5) * 4;
            float4 v = *(const float4*)(W + (size_t)(j0 + rr) * ldw + woff + k0 + k4);
            Ws[k4 + 0][rr] = v.x; Ws[k4 + 1][rr] = v.y;
            Ws[k4 + 2][rr] = v.z; Ws[k4 + 3][rr] = v.w;
        }
        __syncthreads();
        #pragma unroll
        for (int k = 0; k < KT; ++k) {
            float2 wv = *(const float2*)&Ws[k][r0];
            float2 w0 = make_float2(wv.x, wv.x);
            float2 w1 = make_float2(wv.y, wv.y);
            float4 a0 = *(const float4*)&As[k][b0];
            float4 a1 = *(const float4*)&As[k][b0 + 4];
            float2 ap[4] = { {a0.x,a0.y},{a0.z,a0.w},{a1.x,a1.y},{a1.z,a1.w} };
            #pragma unroll
            for (int p = 0; p < 4; ++p) {
                acc[0][p] = ffma2(ap[p], w0, acc[0][p]);
                acc[1][p] = ffma2(ap[p], w1, acc[1][p]);
            }
        }
        __syncthreads();
    }
    #pragma unroll
    for (int ri = 0; ri < 2; ++ri)
        #pragma unroll
        for (int p = 0; p < 4; ++p) {
            int j = j0 + r0 + ri;
            C[(b0 + 2 * p)     * G3 + j] = acc[ri][p].x;
            C[(b0 + 2 * p + 1) * G3 + j] = acc[ri][p].y;
        }
}

// one-time: gi_ctx = ctx @ W_ih[:, E:]^T
__global__ void __launch_bounds__(128) k_gictx(const float* __restrict__ W_ih) {
    gemm64x32(g_ctx, nullptr, W_ih, EE + HH, EE, blockIdx.x * 32, HH, g_gictx);
}

// per-step: gi (emb part) and gh in one launch
__global__ void __launch_bounds__(128) k_pregates(int cur,
        const float* __restrict__ W_ih, const float* __restrict__ W_hh,
        const float* __restrict__ emb_table) {
    int bx = blockIdx.x;
    if (bx < 96) gemm64x32(nullptr, emb_table, W_ih, EE + HH, 0, bx * 32, EE, g_giacc);
    else         gemm64x32(g_h[cur], nullptr,  W_hh, HH,      0, (bx - 96) * 32, HH, g_ghacc);
}

// ---------------- GRU gates ----------------
__global__ void __launch_bounds__(256) k_gates(int cur,
        const float* __restrict__ b_ih, const float* __restrict__ b_hh,
        float* __restrict__ out_h) {
    int idx = blockIdx.x * 256 + threadIdx.x;   // < 65536
    int b = idx >> 10, i = idx & 1023;
    int base = b * G3;
    float gir = g_giacc[base + i]        + g_gictx[base + i]        + b_ih[i];
    float giz = g_giacc[base + 1024 + i] + g_gictx[base + 1024 + i] + b_ih[1024 + i];
    float gin = g_giacc[base + 2048 + i] + g_gictx[base + 2048 + i] + b_ih[2048 + i];
    float ghr = g_ghacc[base + i]        + b_hh[i];
    float ghz = g_ghacc[base + 1024 + i] + b_hh[1024 + i];
    float ghn = g_ghacc[base + 2048 + i] + b_hh[2048 + i];
    float r = 1.f / (1.f + expf(-(gir + ghr)));
    float z = 1.f / (1.f + expf(-(giz + ghz)));
    float n = tanhf(gin + r * ghn);
    float h = g_h[cur][idx];
    float hn = (1.f - z) * n + z * h;
    g_h[cur ^ 1][idx] = hn;
    if (out_h) out_h[idx] = hn;
}

// ---------------- logits GEMM (64 x 32000, K=1024) + partial argmax ----------------
#define KT2 16
__global__ void __launch_bounds__(256) k_logits(int hsel,
        const float* __restrict__ W_out, const float* __restrict__ b_out,
        float* __restrict__ outL, int t) {
    __shared__ float As[KT2][68];
    __shared__ float Ws[KT2][132];
    const int tid = threadIdx.x, bx = blockIdx.x;
    const int vblk = bx * 128;
    const int vthr = tid & 31, bthr = tid >> 5;
    const int v0 = vthr * 4, b0 = bthr * 8;
    const float* __restrict__ hn = g_h[hsel];
    float2 acc[4][4] = {};

    for (int k0 = 0; k0 < HH; k0 += KT2) {
        {   // A: 64 x 16 = 1024 floats, 1 float4 per thread
            int bb = tid & 63, k4 = (tid >> 6) * 4;
            float4 v = *(const float4*)(hn + (size_t)bb * HH + k0 + k4);
            As[k4 + 0][bb] = v.x; As[k4 + 1][bb] = v.y;
            As[k4 + 2][bb] = v.z; As[k4 + 3][bb] = v.w;
        }
        #pragma unroll
        for (int r = 0; r < 2; ++r) {  // W: 128 x 16 = 2048 floats, 2 float4 per thread
            int idx = r * 256 + tid;
            int vv = idx & 127, k4 = (idx >> 7) * 4;
            float4 w = *(const float4*)(W_out + (size_t)(vblk + vv) * HH + k0 + k4);
            Ws[k4 + 0][vv] = w.x; Ws[k4 + 1][vv] = w.y;
            Ws[k4 + 2][vv] = w.z; Ws[k4 + 3][vv] = w.w;
        }
        __syncthreads();
        #pragma unroll
        for (int k = 0; k < KT2; ++k) {
            float4 a0 = *(const float4*)&As[k][b0];
            float4 a1 = *(const float4*)&As[k][b0 + 4];
            float2 ap[4] = { {a0.x,a0.y},{a0.z,a0.w},{a1.x,a1.y},{a1.z,a1.w} };
            float4 wv = *(const float4*)&Ws[k][v0];
            float2 wd[4] = { {wv.x,wv.x},{wv.y,wv.y},{wv.z,wv.z},{wv.w,wv.w} };
            #pragma unroll
            for (int p = 0; p < 4; ++p)
                #pragma unroll
                for (int vi = 0; vi < 4; ++vi)
                    acc[p][vi] = ffma2(ap[p], wd[vi], acc[p][vi]);
        }
        __syncthreads();
    }

    float4 bias = *(const float4*)(b_out + vblk + v0);
    float bb4[4] = { bias.x, bias.y, bias.z, bias.w };

    float bestv[8]; int besti[8];
    #pragma unroll
    for (int p = 0; p < 4; ++p) {
        float lg0[4], lg1[4];
        #pragma unroll
        for (int vi = 0; vi < 4; ++vi) {
            lg0[vi] = acc[p][vi].x + bb4[vi];
            lg1[vi] = acc[p][vi].y + bb4[vi];
        }
        int b_lo = b0 + 2 * p, b_hi = b_lo + 1;
        float4 s0 = { lg0[0], lg0[1], lg0[2], lg0[3] };
        float4 s1 = { lg1[0], lg1[1], lg1[2], lg1[3] };
        *(float4*)(outL + (size_t)b_lo * TT * VV + (size_t)t * VV + vblk + v0) = s0;
        *(float4*)(outL + (size_t)b_hi * TT * VV + (size_t)t * VV + vblk + v0) = s1;
        float bv = lg0[0]; int bi = 0;
        #pragma unroll
        for (int vi = 1; vi < 4; ++vi) if (lg0[vi] > bv) { bv = lg0[vi]; bi = vi; }
        bestv[2 * p] = bv; besti[2 * p] = vblk + v0 + bi;
        bv = lg1[0]; bi = 0;
        #pragma unroll
        for (int vi = 1; vi < 4; ++vi) if (lg1[vi] > bv) { bv = lg1[vi]; bi = vi; }
        bestv[2 * p + 1] = bv; besti[2 * p + 1] = vblk + v0 + bi;
    }
    // warp-reduce 8 independent (per-b) argmaxes (first-index tie-break)
    #pragma unroll
    for (int s = 0; s < 8; ++s) {
        float v = bestv[s]; int i = besti[s];
        #pragma unroll
        for (int o = 16; o; o >>= 1) {
            float ov = __shfl_down_sync(0xffffffffu, v, o);
            int   oi = __shfl_down_sync(0xffffffffu, i, o);
            if (ov > v || (ov == v && oi < i)) { v = ov; i = oi; }
        }
        if ((tid & 31) == 0) {
            int b = b0 + s;
            g_pv[b * NLBLK + bx] = v;
            g_pi[b * NLBLK + bx] = i;
        }
    }
}

// ---------------- argmax finalize -> next tokens ----------------
__global__ void __launch_bounds__(256) k_amax_fin() {
    int b = blockIdx.x, tid = threadIdx.x;
    float v = -1e30f; int i = 0x7fffffff;
    for (int p = tid; p < NLBLK; p += 256) {
        float pv = g_pv[b * NLBLK + p]; int pi = g_pi[b * NLBLK + p];
        if (pv > v || (pv == v && pi < i)) { v = pv; i = pi; }
    }
    __shared__ float sv[256]; __shared__ int si[256];
    sv[tid] = v; si[tid] = i; __syncthreads();
    for (int s = 128; s; s >>= 1) {
        if (tid < s) {
            if (sv[tid + s] > sv[tid] || (sv[tid + s] == sv[tid] && si[tid + s] < si[tid])) {
                sv[tid] = sv[tid + s]; si[tid] = si[tid + s];
            }
        }
        __syncthreads();
    }
    if (!tid) g_tok[b] = si[0];
}

// ---------------- host: launch sequence (graph-capturable) ----------------
extern "C" void kernel_launch(void* const* d_in, const int* in_sizes, int n_in,
                              void* d_out, int out_size) {
    const float* enc    = (const float*)d_in[0];   // [B,S,H]
    const float* eh     = (const float*)d_in[1];   // [1,B,H]
    const float* embt   = (const float*)d_in[2];   // [V,E]
    // d_in[3] = Wa: provably unused (softmax shift invariance)
    const float* Ua     = (const float*)d_in[4];
    const float* Va     = (const float*)d_in[5];
    const float* W_ih   = (const float*)d_in[6];   // [3H, E+H]
    const float* W_hh   = (const float*)d_in[7];   // [3H, H]
    const float* b_ih   = (const float*)d_in[8];
    const float* b_hh   = (const float*)d_in[9];
    const float* W_out  = (const float*)d_in[10];  // [V, H]
    const float* b_out  = (const float*)d_in[11];

    float* outL = (float*)d_out;                       // [B,T,V]
    float* outH = outL + (size_t)BB * TT * VV;         // [1,B,H]
    float* outA = outH + (size_t)BB * HH;              // [B,T,S]

    k_init<<<(BB * HH + 255) / 256, 256>>>(eh);
    k_u<<<HH / 256, 256>>>(Ua, Va);
    k_attn<<<BB, 128>>>(enc, outA);
    k_gictx<<<96, 128>>>(W_ih);

    for (int t = 0; t < TT; ++t) {
        int cur = t & 1;
        k_pregates<<<192, 128>>>(cur, W_ih, W_hh, embt);
        k_gates<<<BB * HH / 256, 256>>>(cur, b_ih, b_hh, (t == TT - 1) ? outH : nullptr);
        k_logits<<<NLBLK, 256>>>(cur ^ 1, W_out, b_out, outL, t);
        if (t < TT - 1) k_amax_fin<<<BB, 256>>>();
    }
}

// round 2
// speedup vs baseline: 1.0064x; 1.0064x over previous
#include <cuda_runtime.h>
#include <math.h>

#define BB 64
#define SS 96
#define HH 1024
#define EE 512
#define VV 32000
#define TT 32
#define G3 3072
#define NLBLK 250   // 32000 / 128

// ---------------- device scratch (static, no allocations) ----------------
__device__ float g_u[HH];                 // u = Ua^T @ Va
__device__ float g_ctx[BB * HH];          // attention context (step-invariant)
__device__ float g_gictx[BB * G3];        // ctx @ W_ih[:,E:]^T (step-invariant)
__device__ float g_giacc[BB * G3];        // per-step emb @ W_ih[:, :E]^T
__device__ float g_ghacc[BB * G3];        // per-step h @ W_hh^T
__device__ float g_h[2][BB * HH];         // hidden state ping-pong
__device__ int   g_tok[BB];               // current tokens
__device__ float g_pv[BB * NLBLK];        // argmax partials (value)
__device__ int   g_pi[BB * NLBLK];        // argmax partials (index)

// ---------------- packed fp32x2 FMA (Blackwell) ----------------
union F2U { float2 f; unsigned long long u; };
__device__ __forceinline__ float2 ffma2(float2 a, float2 b, float2 c) {
    F2U A, B, C, D;
    A.f = a; B.f = b; C.f = c;
    asm("fma.rn.f32x2 %0, %1, %2, %3;" : "=l"(D.u) : "l"(A.u), "l"(B.u), "l"(C.u));
    return D.f;
}

// ---------------- init: h0 <- encoder_hidden, tok <- START ----------------
__global__ void k_init(const float* __restrict__ eh) {
    int i = blockIdx.x * blockDim.x + threadIdx.x;
    if (i < BB * HH) g_h[0][i] = eh[i];
    if (i < BB)      g_tok[i] = 1;
}

// ---------------- u[h] = sum_g Va[g] * Ua[g,h] ----------------
__global__ void __launch_bounds__(256) k_u(const float* __restrict__ Ua,
                                           const float* __restrict__ Va) {
    __shared__ float sva[HH];
    for (int i = threadIdx.x; i < HH; i += 256) sva[i] = Va[i];
    __syncthreads();
    int h = blockIdx.x * 256 + threadIdx.x;
    float acc = 0.f;
    for (int g = 0; g < HH; ++g) acc = fmaf(sva[g], Ua[(size_t)g * HH + h], acc);
    g_u[h] = acc;
}

// ---------------- attention: scores, softmax, ctx, write attentions ----------------
__global__ void __launch_bounds__(128) k_attn(const float* __restrict__ keys,
                                              float* __restrict__ out_attn) {
    __shared__ float s_w[SS];
    __shared__ float s_u[HH];
    int b = blockIdx.x, tid = threadIdx.x;
    for (int i = tid; i < HH; i += 128) s_u[i] = g_u[i];
    __syncthreads();

    int warp = tid >> 5, lane = tid & 31;
    const float* kb = keys + (size_t)b * SS * HH;

    for (int s = warp; s < SS; s += 4) {
        const float* kr = kb + (size_t)s * HH;
        float acc = 0.f;
        for (int k = lane; k < HH; k += 32) acc = fmaf(kr[k], s_u[k], acc);
        #pragma unroll
        for (int o = 16; o; o >>= 1) acc += __shfl_down_sync(0xffffffffu, acc, o);
        if (!lane) s_w[s] = acc;
    }
    __syncthreads();

    if (warp == 0) {
        float m = -1e30f;
        for (int s = lane; s < SS; s += 32) m = fmaxf(m, s_w[s]);
        #pragma unroll
        for (int o = 16; o; o >>= 1) m = fmaxf(m, __shfl_xor_sync(0xffffffffu, m, o));
        float sum = 0.f;
        for (int s = lane; s < SS; s += 32) { float e = expf(s_w[s] - m); s_w[s] = e; sum += e; }
        #pragma unroll
        for (int o = 16; o; o >>= 1) sum += __shfl_xor_sync(0xffffffffu, sum, o);
        float inv = 1.f / sum;
        for (int s = lane; s < SS; s += 32) s_w[s] *= inv;
    }
    __syncthreads();

    // ctx[b,h] = sum_s w[s]*keys[b,s,h]
    for (int h = tid; h < HH; h += 128) {
        float acc = 0.f;
        for (int s = 0; s < SS; ++s) acc = fmaf(s_w[s], kb[(size_t)s * HH + h], acc);
        g_ctx[b * HH + h] = acc;
    }
    // attentions are step-invariant: replicate over T
    float* oa = out_attn + (size_t)b * TT * SS;
    for (int e = tid; e < TT * SS; e += 128) oa[e] = s_w[e % SS];
}

// ---------------- generic 64(b) x 32(rows) GEMM tile, K-loop, f32x2 ----------------
// C[b*G3 + j0+r] += sum_k A(b,k) * W[(j0+r)*ldw + woff + k]
// A mode: Aptr != null -> dense [64,K]; else emb-gather: relu(emb_table[tok[b]*EE + k])
#define KT 32
__device__ __forceinline__ void gemm64x32(
    const float* __restrict__ Aptr, const float* __restrict__ emb_table,
    const float* __restrict__ W, int ldw, int woff,
    int j0, int K, float* __restrict__ C)
{
    __shared__ float As[KT][68];
    __shared__ float Ws[KT][36];
    __shared__ int stok[BB];
    const int tid = threadIdx.x;  // 128 threads
    if (Aptr == nullptr && tid < BB) stok[tid] = g_tok[tid];
    __syncthreads();

    const int rthr = tid & 15, bthr = tid >> 4;
    const int r0 = rthr * 2, b0 = bthr * 8;
    float2 acc[2][4] = {};

    for (int k0 = 0; k0 < K; k0 += KT) {
        // A tile: 64 x 32 = 2048 floats, 4 float4 per thread
        #pragma unroll
        for (int r = 0; r < 4; ++r) {
            int idx = r * 128 + tid;
            int bb = idx & 63, k4 = (idx >> 6) * 4;
            float4 v;
            if (Aptr) v = *(const float4*)(Aptr + (size_t)bb * K + k0 + k4);
            else {
                v = *(const float4*)(emb_table + (size_t)stok[bb] * EE + k0 + k4);
                v.x = fmaxf(v.x, 0.f); v.y = fmaxf(v.y, 0.f);
                v.z = fmaxf(v.z, 0.f); v.w = fmaxf(v.w, 0.f);
            }
            As[k4 + 0][bb] = v.x; As[k4 + 1][bb] = v.y;
            As[k4 + 2][bb] = v.z; As[k4 + 3][bb] = v.w;
        }
        // W tile: 32 rows x 32 k = 1024 floats, 2 float4 per thread
        #pragma unroll
        for (int r = 0; r < 2; ++r) {
            int idx = r * 128 + tid;
            int rr = idx & 31, k4 = (idx >> 5) * 4;
            float4 v = *(const float4*)(W + (size_t)(j0 + rr) * ldw + woff + k0 + k4);
            Ws[k4 + 0][rr] = v.x; Ws[k4 + 1][rr] = v.y;
            Ws[k4 + 2][rr] = v.z; Ws[k4 + 3][rr] = v.w;
        }
        __syncthreads();
        #pragma unroll
        for (int k = 0; k < KT; ++k) {
            float2 wv = *(const float2*)&Ws[k][r0];
            float2 w0 = make_float2(wv.x, wv.x);
            float2 w1 = make_float2(wv.y, wv.y);
            float4 a0 = *(const float4*)&As[k][b0];
            float4 a1 = *(const float4*)&As[k][b0 + 4];
            float2 ap[4] = { {a0.x,a0.y},{a0.z,a0.w},{a1.x,a1.y},{a1.z,a1.w} };
            #pragma unroll
            for (int p = 0; p < 4; ++p) {
                acc[0][p] = ffma2(ap[p], w0, acc[0][p]);
                acc[1][p] = ffma2(ap[p], w1, acc[1][p]);
            }
        }
        __syncthreads();
    }
    #pragma unroll
    for (int ri = 0; ri < 2; ++ri)
        #pragma unroll
        for (int p = 0; p < 4; ++p) {
            int j = j0 + r0 + ri;
            C[(b0 + 2 * p)     * G3 + j] = acc[ri][p].x;
            C[(b0 + 2 * p + 1) * G3 + j] = acc[ri][p].y;
        }
}

// one-time: gi_ctx = ctx @ W_ih[:, E:]^T
__global__ void __launch_bounds__(128) k_gictx(const float* __restrict__ W_ih) {
    gemm64x32(g_ctx, nullptr, W_ih, EE + HH, EE, blockIdx.x * 32, HH, g_gictx);
}

// per-step: gi (emb part) and gh in one launch
__global__ void __launch_bounds__(128) k_pregates(int cur,
        const float* __restrict__ W_ih, const float* __restrict__ W_hh,
        const float* __restrict__ emb_table) {
    int bx = blockIdx.x;
    if (bx < 96) gemm64x32(nullptr, emb_table, W_ih, EE + HH, 0, bx * 32, EE, g_giacc);
    else         gemm64x32(g_h[cur], nullptr,  W_hh, HH,      0, (bx - 96) * 32, HH, g_ghacc);
}

// ---------------- GRU gates ----------------
__global__ void __launch_bounds__(256) k_gates(int cur,
        const float* __restrict__ b_ih, const float* __restrict__ b_hh,
        float* __restrict__ out_h) {
    int idx = blockIdx.x * 256 + threadIdx.x;   // < 65536
    int b = idx >> 10, i = idx & 1023;
    int base = b * G3;
    float gir = g_giacc[base + i]        + g_gictx[base + i]        + b_ih[i];
    float giz = g_giacc[base + 1024 + i] + g_gictx[base + 1024 + i] + b_ih[1024 + i];
    float gin = g_giacc[base + 2048 + i] + g_gictx[base + 2048 + i] + b_ih[2048 + i];
    float ghr = g_ghacc[base + i]        + b_hh[i];
    float ghz = g_ghacc[base + 1024 + i] + b_hh[1024 + i];
    float ghn = g_ghacc[base + 2048 + i] + b_hh[2048 + i];
    float r = 1.f / (1.f + expf(-(gir + ghr)));
    float z = 1.f / (1.f + expf(-(giz + ghz)));
    float n = tanhf(gin + r * ghn);
    float h = g_h[cur][idx];
    float hn = (1.f - z) * n + z * h;
    g_h[cur ^ 1][idx] = hn;
    if (out_h) out_h[idx] = hn;
}

// ---------------- logits GEMM (64 x 32000, K=1024) + partial argmax ----------------
#define KT2 16
__global__ void __launch_bounds__(256) k_logits(int hsel,
        const float* __restrict__ W_out, const float* __restrict__ b_out,
        float* __restrict__ outL, int t) {
    __shared__ float As[KT2][68];
    __shared__ float Ws[KT2][132];
    const int tid = threadIdx.x, bx = blockIdx.x;
    const int vblk = bx * 128;
    const int vthr = tid & 31, bthr = tid >> 5;
    const int v0 = vthr * 4, b0 = bthr * 8;
    const float* __restrict__ hn = g_h[hsel];
    float2 acc[4][4] = {};

    for (int k0 = 0; k0 < HH; k0 += KT2) {
        {   // A: 64 x 16 = 1024 floats, 1 float4 per thread
            int bb = tid & 63, k4 = (tid >> 6) * 4;
            float4 v = *(const float4*)(hn + (size_t)bb * HH + k0 + k4);
            As[k4 + 0][bb] = v.x; As[k4 + 1][bb] = v.y;
            As[k4 + 2][bb] = v.z; As[k4 + 3][bb] = v.w;
        }
        #pragma unroll
        for (int r = 0; r < 2; ++r) {  // W: 128 x 16 = 2048 floats, 2 float4 per thread
            int idx = r * 256 + tid;
            int vv = idx & 127, k4 = (idx >> 7) * 4;
            float4 w = *(const float4*)(W_out + (size_t)(vblk + vv) * HH + k0 + k4);
            Ws[k4 + 0][vv] = w.x; Ws[k4 + 1][vv] = w.y;
            Ws[k4 + 2][vv] = w.z; Ws[k4 + 3][vv] = w.w;
        }
        __syncthreads();
        #pragma unroll
        for (int k = 0; k < KT2; ++k) {
            float4 a0 = *(const float4*)&As[k][b0];
            float4 a1 = *(const float4*)&As[k][b0 + 4];
            float2 ap[4] = { {a0.x,a0.y},{a0.z,a0.w},{a1.x,a1.y},{a1.z,a1.w} };
            float4 wv = *(const float4*)&Ws[k][v0];
            float2 wd[4] = { {wv.x,wv.x},{wv.y,wv.y},{wv.z,wv.z},{wv.w,wv.w} };
            #pragma unroll
            for (int p = 0; p < 4; ++p)
                #pragma unroll
                for (int vi = 0; vi < 4; ++vi)
                    acc[p][vi] = ffma2(ap[p], wd[vi], acc[p][vi]);
        }
        __syncthreads();
    }

    float4 bias = *(const float4*)(b_out + vblk + v0);
    float bb4[4] = { bias.x, bias.y, bias.z, bias.w };

    float bestv[8]; int besti[8];
    #pragma unroll
    for (int p = 0; p < 4; ++p) {
        float lg0[4], lg1[4];
        #pragma unroll
        for (int vi = 0; vi < 4; ++vi) {
            lg0[vi] = acc[p][vi].x + bb4[vi];
            lg1[vi] = acc[p][vi].y + bb4[vi];
        }
        int b_lo = b0 + 2 * p, b_hi = b_lo + 1;
        float4 s0 = { lg0[0], lg0[1], lg0[2], lg0[3] };
        float4 s1 = { lg1[0], lg1[1], lg1[2], lg1[3] };
        *(float4*)(outL + (size_t)b_lo * TT * VV + (size_t)t * VV + vblk + v0) = s0;
        *(float4*)(outL + (size_t)b_hi * TT * VV + (size_t)t * VV + vblk + v0) = s1;
        float bv = lg0[0]; int bi = 0;
        #pragma unroll
        for (int vi = 1; vi < 4; ++vi) if (lg0[vi] > bv) { bv = lg0[vi]; bi = vi; }
        bestv[2 * p] = bv; besti[2 * p] = vblk + v0 + bi;
        bv = lg1[0]; bi = 0;
        #pragma unroll
        for (int vi = 1; vi < 4; ++vi) if (lg1[vi] > bv) { bv = lg1[vi]; bi = vi; }
        bestv[2 * p + 1] = bv; besti[2 * p + 1] = vblk + v0 + bi;
    }
    // warp-reduce 8 independent (per-b) argmaxes (first-index tie-break)
    #pragma unroll
    for (int s = 0; s < 8; ++s) {
        float v = bestv[s]; int i = besti[s];
        #pragma unroll
        for (int o = 16; o; o >>= 1) {
            float ov = __shfl_down_sync(0xffffffffu, v, o);
            int   oi = __shfl_down_sync(0xffffffffu, i, o);
            if (ov > v || (ov == v && oi < i)) { v = ov; i = oi; }
        }
        if ((tid & 31) == 0) {
            int b = b0 + s;
            g_pv[b * NLBLK + bx] = v;
            g_pi[b * NLBLK + bx] = i;
        }
    }
}

// ---------------- argmax finalize -> next tokens ----------------
__global__ void __launch_bounds__(256) k_amax_fin() {
    int b = blockIdx.x, tid = threadIdx.x;
    float v = -1e30f; int i = 0x7fffffff;
    for (int p = tid; p < NLBLK; p += 256) {
        float pv = g_pv[b * NLBLK + p]; int pi = g_pi[b * NLBLK + p];
        if (pv > v || (pv == v && pi < i)) { v = pv; i = pi; }
    }
    __shared__ float sv[256]; __shared__ int si[256];
    sv[tid] = v; si[tid] = i; __syncthreads();
    for (int s = 128; s; s >>= 1) {
        if (tid < s) {
            if (sv[tid + s] > sv[tid] || (sv[tid + s] == sv[tid] && si[tid + s] < si[tid])) {
                sv[tid] = sv[tid + s]; si[tid] = si[tid + s];
            }
        }
        __syncthreads();
    }
    if (!tid) g_tok[b] = si[0];
}

// ---------------- host: launch sequence (graph-capturable) ----------------
extern "C" void kernel_launch(void* const* d_in, const int* in_sizes, int n_in,
                              void* d_out, int out_size) {
    const float* enc    = (const float*)d_in[0];   // [B,S,H]
    const float* eh     = (const float*)d_in[1];   // [1,B,H]
    const float* embt   = (const float*)d_in[2];   // [V,E]
    // d_in[3] = Wa: provably unused (softmax shift invariance)
    const float* Ua     = (const float*)d_in[4];
    const float* Va     = (const float*)d_in[5];
    const float* W_ih   = (const float*)d_in[6];   // [3H, E+H]
    const float* W_hh   = (const float*)d_in[7];   // [3H, H]
    const float* b_ih   = (const float*)d_in[8];
    const float* b_hh   = (const float*)d_in[9];
    const float* W_out  = (const float*)d_in[10];  // [V, H]
    const float* b_out  = (const float*)d_in[11];

    float* outL = (float*)d_out;                       // [B,T,V]
    float* outH = outL + (size_t)BB * TT * VV;         // [1,B,H]
    float* outA = outH + (size_t)BB * HH;              // [B,T,S]

    k_init<<<(BB * HH + 255) / 256, 256>>>(eh);
    k_u<<<HH / 256, 256>>>(Ua, Va);
    k_attn<<<BB, 128>>>(enc, outA);
    k_gictx<<<96, 128>>>(W_ih);

    for (int t = 0; t < TT; ++t) {
        int cur = t & 1;
        k_pregates<<<192, 128>>>(cur, W_ih, W_hh, embt);
        k_gates<<<BB * HH / 256, 256>>>(cur, b_ih, b_hh, (t == TT - 1) ? outH : nullptr);
        k_logits<<<NLBLK, 256>>>(cur ^ 1, W_out, b_out, outL, t);
        if (t < TT - 1) k_amax_fin<<<BB, 256>>>();
    }
}